// round 1
// baseline (speedup 1.0000x reference)
#include <cuda_runtime.h>
#include <cuda_bf16.h>
#include <cstdint>

// Problem constants (fixed shapes from reference setup_inputs)
#define NB   8
#define CIN  64
#define OUT  64
#define HH   128
#define WW   128
#define HW   (HH*WW)          // 16384
#define NPIX (NB*HW)          // 131072
#define KWSTRIDE 576          // C*K*K per output channel in weight tensors
// unfold tap kk = (dy+1)*3 + (dx+1); center kk = 4

typedef unsigned long long ull;

// -------- scratch (static __device__, no allocation) --------
__device__ int  g_count;
__device__ uint2 g_list[NPIX];   // one entry max per pixel: {pixel_id, mask24}

// -------- packed f32x2 fma --------
__device__ __forceinline__ void ffma2(ull& acc, ull a, ull b) {
    asm("fma.rn.f32x2 %0, %1, %2, %0;" : "+l"(acc) : "l"(a), "l"(b));
}

// ============================================================
// Kernel Z: zero the worklist counter
// ============================================================
__global__ void k_zero() {
    if (threadIdx.x == 0) g_count = 0;
}

// ============================================================
// Kernel B: compute rare-tap masks, build worklist.
// One block = one image row (128 pixels), 128 threads.
// ============================================================
__global__ void k_masks(const float* __restrict__ depth,
                        const float* __restrict__ fx) {
    const int n = blockIdx.x >> 7;
    const int h = blockIdx.x & 127;
    const int w = threadIdx.x;

    const float* drow = depth + (size_t)n * HW;
    const float ctr = drow[h * WW + w];
    const float fxv = fx[n];
    const float grid = ctr / fxv;          // IEEE div, matches jnp divide
    const float half = 0.5f * grid;
    const float t0 = ctr + grid;           // branch 0 target
    const float t2 = ctr - grid;           // branch 2 target

    unsigned mask = 0;
    #pragma unroll
    for (int dy = -1; dy <= 1; ++dy) {
        #pragma unroll
        for (int dx = -1; dx <= 1; ++dx) {
            const int kk = (dy + 1) * 3 + (dx + 1);
            if (kk == 4) continue;  // center: m1 always on (dense), m0/m2 provably off
            const int hh = h + dy, ww2 = w + dx;
            if (hh < 0 || hh >= HH || ww2 < 0 || ww2 >= WW) continue; // x padded zero
            const float dv = drow[hh * WW + ww2];
            if (fabsf(dv - t0)  <= half) mask |= 1u << (kk * 3 + 0);
            if (fabsf(dv - ctr) <= half) mask |= 1u << (kk * 3 + 1);
            if (fabsf(dv - t2)  <= half) mask |= 1u << (kk * 3 + 2);
        }
    }
    if (mask) {
        const int pos = atomicAdd(&g_count, 1);
        g_list[pos] = make_uint2((unsigned)(n * HW + h * WW + w), mask);
    }
}

// ============================================================
// Kernel A: dense 1x1 conv, out[n,:,p] = W1_center @ x[n,:,p]
// One block = one image row (128 pixels), 128 threads (4 warps).
// Warp ty handles 16 output channels; lane tx handles pixel
// pairs (2tx,2tx+1) and (64+2tx,65+2tx) as packed f32x2.
// ============================================================
__global__ void __launch_bounds__(128, 4)
k_dense(const float* __restrict__ x,
        const float* __restrict__ w1,
        float* __restrict__ out) {
    __shared__ ull wsh[CIN * OUT];   // (w,w) duplicated pairs: wsh[c*64 + o]

    const int n = blockIdx.x >> 7;
    const int h = blockIdx.x & 127;
    const int t = threadIdx.x;

    // stage duplicated center-tap weights of branch 1
    for (int idx = t; idx < CIN * OUT; idx += 128) {
        const int c = idx >> 6, o = idx & 63;
        const float wv = w1[o * KWSTRIDE + c * 9 + 4];
        float2 d2 = make_float2(wv, wv);
        wsh[idx] = *reinterpret_cast<ull*>(&d2);
    }
    __syncthreads();

    const int tx = t & 31;
    const int obase = (t >> 5) * 16;

    const float* xbase = x + (size_t)n * CIN * HW + h * WW;

    ull acc0[16], acc1[16];
    #pragma unroll
    for (int j = 0; j < 16; ++j) { acc0[j] = 0ull; acc1[j] = 0ull; }

    // prefetch c=0
    const ull* xp = reinterpret_cast<const ull*>(xbase);
    ull xa = xp[tx];
    ull xb = xp[tx + 32];

    #pragma unroll 2
    for (int c = 0; c < CIN; ++c) {
        ull nxa = 0, nxb = 0;
        if (c + 1 < CIN) {
            const ull* np = reinterpret_cast<const ull*>(xbase + (size_t)(c + 1) * HW);
            nxa = np[tx];
            nxb = np[tx + 32];
        }
        const ull* wrow = &wsh[c * OUT + obase];
        #pragma unroll
        for (int j = 0; j < 16; ++j) {
            const ull w2 = wrow[j];
            ffma2(acc0[j], xa, w2);
            ffma2(acc1[j], xb, w2);
        }
        xa = nxa; xb = nxb;
    }

    float* obase_p = out + (size_t)(n * OUT + obase) * HW + h * WW;
    #pragma unroll
    for (int j = 0; j < 16; ++j) {
        ull* po = reinterpret_cast<ull*>(obase_p + (size_t)j * HW);
        po[tx]      = acc0[j];
        po[tx + 32] = acc1[j];
    }
}

// ============================================================
// Kernel C: sparse corrections. One worklist item per block-iter,
// 64 threads = 64 output channels. out += sum over active taps.
// ============================================================
__global__ void k_correct(const float* __restrict__ x,
                          const float* __restrict__ w0,
                          const float* __restrict__ w1,
                          const float* __restrict__ w2,
                          float* __restrict__ out) {
    const int cnt = g_count;
    const int o = threadIdx.x;
    for (int i = blockIdx.x; i < cnt; i += gridDim.x) {
        const uint2 item = g_list[i];
        const unsigned pid = item.x;
        unsigned mask = item.y;
        const int n = pid >> 14;
        const int h = (pid >> 7) & 127;
        const int w = pid & 127;

        float corr = 0.0f;
        while (mask) {
            const int bit = __ffs(mask) - 1;
            mask &= mask - 1;
            const int kk = bit / 3;
            const int b  = bit % 3;
            const int dy = kk / 3 - 1, dx = kk % 3 - 1;
            const float* wb = (b == 0) ? w0 : (b == 1) ? w1 : w2;
            const float* wp = wb + o * KWSTRIDE + kk;
            const float* xp = x + (size_t)n * CIN * HW + (h + dy) * WW + (w + dx);
            float s = 0.0f;
            #pragma unroll 8
            for (int c = 0; c < CIN; ++c)
                s += wp[c * 9] * xp[(size_t)c * HW];
            corr += s;
        }
        out[(size_t)(n * OUT + o) * HW + h * WW + w] += corr;
    }
}

// ============================================================
// launch
// ============================================================
extern "C" void kernel_launch(void* const* d_in, const int* in_sizes, int n_in,
                              void* d_out, int out_size) {
    const float* x     = (const float*)d_in[0];
    const float* depth = (const float*)d_in[1];
    const float* fx    = (const float*)d_in[2];
    const float* w0    = (const float*)d_in[3];
    const float* w1    = (const float*)d_in[4];
    const float* w2    = (const float*)d_in[5];
    float* out = (float*)d_out;

    k_zero<<<1, 32>>>();
    k_masks<<<NB * HH, 128>>>(depth, fx);
    k_dense<<<NB * HH, 128>>>(x, w1, out);
    k_correct<<<2048, 64>>>(x, w0, w1, w2, out);
}

// round 2
// speedup vs baseline: 1.4475x; 1.4475x over previous
#include <cuda_runtime.h>
#include <cuda_bf16.h>
#include <cstdint>

// Problem constants (fixed shapes from reference setup_inputs)
#define NB   8
#define CIN  64
#define OUT  64
#define HH   128
#define WW   128
#define HW   (HH*WW)          // 16384
#define NPIX (NB*HW)          // 131072
#define KWSTRIDE 576          // C*K*K per output channel in weight tensors
// unfold tap kk = (dy+1)*3 + (dx+1); center kk = 4

typedef unsigned long long ull;

// -------- scratch (static __device__, no allocation) --------
__device__ int   g_count;
__device__ uint2 g_list[NPIX];                 // {pixel_id, mask24}, one per pixel max
__device__ float g_wpack[3 * 9 * CIN * OUT];   // wpack[(b*9+kk)*4096 + c*64 + o]

// -------- packed f32x2 fma --------
__device__ __forceinline__ void ffma2(ull& acc, ull a, ull b) {
    asm("fma.rn.f32x2 %0, %1, %2, %0;" : "+l"(acc) : "l"(a), "l"(b));
}

// ============================================================
// Kernel P: prep — zero worklist counter + repack weights to
// wpack[b][kk][c][o] for coalesced reads in k_correct.
// grid = 27 blocks (b*9+kk), 64 threads (o).
// ============================================================
__global__ void k_prep(const float* __restrict__ w0,
                       const float* __restrict__ w1,
                       const float* __restrict__ w2) {
    if (blockIdx.x == 0 && threadIdx.x == 0) g_count = 0;
    const int b  = blockIdx.x / 9;
    const int kk = blockIdx.x % 9;
    const float* wb = (b == 0) ? w0 : (b == 1) ? w1 : w2;
    const int o = threadIdx.x;
    float* dst = g_wpack + (size_t)blockIdx.x * (CIN * OUT);
    #pragma unroll 8
    for (int c = 0; c < CIN; ++c)
        dst[c * OUT + o] = wb[o * KWSTRIDE + c * 9 + kk];
}

// ============================================================
// Kernel B: compute rare-tap masks, build worklist.
// One block = one image row (128 pixels), 128 threads.
// ============================================================
__global__ void k_masks(const float* __restrict__ depth,
                        const float* __restrict__ fx) {
    const int n = blockIdx.x >> 7;
    const int h = blockIdx.x & 127;
    const int w = threadIdx.x;

    const float* drow = depth + (size_t)n * HW;
    const float ctr = drow[h * WW + w];
    const float fxv = fx[n];
    const float grid = ctr / fxv;          // IEEE div, matches jnp divide
    const float half = 0.5f * grid;
    const float t0 = ctr + grid;           // branch 0 target
    const float t2 = ctr - grid;           // branch 2 target

    unsigned mask = 0;
    #pragma unroll
    for (int dy = -1; dy <= 1; ++dy) {
        #pragma unroll
        for (int dx = -1; dx <= 1; ++dx) {
            const int kk = (dy + 1) * 3 + (dx + 1);
            if (kk == 4) continue;  // center: m1 always on (dense), m0/m2 provably off
            const int hh = h + dy, ww2 = w + dx;
            if (hh < 0 || hh >= HH || ww2 < 0 || ww2 >= WW) continue; // x padded zero
            const float dv = drow[hh * WW + ww2];
            if (fabsf(dv - t0)  <= half) mask |= 1u << (kk * 3 + 0);
            if (fabsf(dv - ctr) <= half) mask |= 1u << (kk * 3 + 1);
            if (fabsf(dv - t2)  <= half) mask |= 1u << (kk * 3 + 2);
        }
    }
    if (mask) {
        const int pos = atomicAdd(&g_count, 1);
        g_list[pos] = make_uint2((unsigned)(n * HW + h * WW + w), mask);
    }
}

// ============================================================
// Kernel A: dense 1x1 conv, out[n,:,p] = W1_center @ x[n,:,p]
// One block = one image row (128 pixels), 128 threads (4 warps).
// Warp handles 16 output channels; lane tx handles pixel
// pairs (2tx,2tx+1) and (64+2tx,65+2tx) as packed f32x2.
// ============================================================
__global__ void __launch_bounds__(128, 4)
k_dense(const float* __restrict__ x,
        const float* __restrict__ w1,
        float* __restrict__ out) {
    __shared__ ull wsh[CIN * OUT];   // (w,w) duplicated pairs: wsh[c*64 + o]

    const int n = blockIdx.x >> 7;
    const int h = blockIdx.x & 127;
    const int t = threadIdx.x;

    // stage duplicated center-tap weights of branch 1
    for (int idx = t; idx < CIN * OUT; idx += 128) {
        const int c = idx >> 6, o = idx & 63;
        const float wv = w1[o * KWSTRIDE + c * 9 + 4];
        float2 d2 = make_float2(wv, wv);
        wsh[idx] = *reinterpret_cast<ull*>(&d2);
    }
    __syncthreads();

    const int tx = t & 31;
    const int obase = (t >> 5) * 16;

    const float* xbase = x + (size_t)n * CIN * HW + h * WW;

    ull acc0[16], acc1[16];
    #pragma unroll
    for (int j = 0; j < 16; ++j) { acc0[j] = 0ull; acc1[j] = 0ull; }

    // prefetch c=0
    const ull* xp = reinterpret_cast<const ull*>(xbase);
    ull xa = xp[tx];
    ull xb = xp[tx + 32];

    #pragma unroll 2
    for (int c = 0; c < CIN; ++c) {
        ull nxa = 0, nxb = 0;
        if (c + 1 < CIN) {
            const ull* np = reinterpret_cast<const ull*>(xbase + (size_t)(c + 1) * HW);
            nxa = np[tx];
            nxb = np[tx + 32];
        }
        const ulonglong2* wrow =
            reinterpret_cast<const ulonglong2*>(&wsh[c * OUT + obase]);
        #pragma unroll
        for (int j = 0; j < 8; ++j) {
            const ulonglong2 w2 = wrow[j];      // LDS.128: two duplicated weights
            ffma2(acc0[2 * j],     xa, w2.x);
            ffma2(acc1[2 * j],     xb, w2.x);
            ffma2(acc0[2 * j + 1], xa, w2.y);
            ffma2(acc1[2 * j + 1], xb, w2.y);
        }
        xa = nxa; xb = nxb;
    }

    float* obase_p = out + (size_t)(n * OUT + obase) * HW + h * WW;
    #pragma unroll
    for (int j = 0; j < 16; ++j) {
        ull* po = reinterpret_cast<ull*>(obase_p + (size_t)j * HW);
        po[tx]      = acc0[j];
        po[tx + 32] = acc1[j];
    }
}

// ============================================================
// Kernel C: sparse corrections. One worklist item (pixel) at a
// time per block; 64 threads. For each active (tap,branch):
//   stage x[:, h+dy, w+dx] into smem (thread = channel),
//   then thread o accumulates sum_c wpack[b,kk,c,o]*xs[c]
// with wpack reads fully coalesced.
// ============================================================
__global__ void __launch_bounds__(64)
k_correct(const float* __restrict__ x,
          float* __restrict__ out) {
    __shared__ float xs[CIN];
    const int cnt = g_count;
    const int o = threadIdx.x;

    for (int i = blockIdx.x; i < cnt; i += gridDim.x) {
        const uint2 item = g_list[i];
        const unsigned pid = item.x;
        unsigned mask = item.y;
        const int n = pid >> 14;
        const int h = (pid >> 7) & 127;
        const int w = pid & 127;
        const float* xpix = x + (size_t)n * CIN * HW;

        float corr = 0.0f;
        while (mask) {
            const int bit = __ffs(mask) - 1;
            mask &= mask - 1;
            const int kk = bit / 3;
            const int b  = bit % 3;
            const int dy = kk / 3 - 1, dx = kk % 3 - 1;

            __syncthreads();   // protect xs from previous tap's readers
            xs[o] = xpix[(size_t)o * HW + (h + dy) * WW + (w + dx)];
            __syncthreads();

            const float* wp = g_wpack + (size_t)(b * 9 + kk) * (CIN * OUT) + o;
            float s = 0.0f;
            #pragma unroll 16
            for (int c = 0; c < CIN; ++c)
                s += wp[(size_t)c * OUT] * xs[c];
            corr += s;
        }
        out[(size_t)(n * OUT + o) * HW + h * WW + w] += corr;
    }
}

// ============================================================
// launch
// ============================================================
extern "C" void kernel_launch(void* const* d_in, const int* in_sizes, int n_in,
                              void* d_out, int out_size) {
    const float* x     = (const float*)d_in[0];
    const float* depth = (const float*)d_in[1];
    const float* fx    = (const float*)d_in[2];
    const float* w0    = (const float*)d_in[3];
    const float* w1    = (const float*)d_in[4];
    const float* w2    = (const float*)d_in[5];
    float* out = (float*)d_out;

    k_prep<<<27, 64>>>(w0, w1, w2);
    k_masks<<<NB * HH, 128>>>(depth, fx);
    k_dense<<<NB * HH, 128>>>(x, w1, out);
    k_correct<<<1024, 64>>>(x, out);
}

// round 3
// speedup vs baseline: 1.4706x; 1.0159x over previous
#include <cuda_runtime.h>
#include <cuda_bf16.h>
#include <cstdint>

// Problem constants (fixed shapes from reference setup_inputs)
#define NB   8
#define CIN  64
#define OUT  64
#define HH   128
#define WW   128
#define HW   (HH*WW)          // 16384
#define NPIX (NB*HW)          // 131072
#define KWSTRIDE 576          // C*K*K per output channel in weight tensors
// unfold tap kk = (dy+1)*3 + (dx+1); center kk = 4

typedef unsigned long long ull;

// -------- scratch (static __device__, no allocation) --------
__device__ int   g_count;
__device__ uint2 g_list[NPIX];                 // {pixel_id, mask24}, one per pixel max
__device__ float g_wpack[3 * 9 * CIN * OUT];   // wpack[(b*9+kk)*4096 + c*64 + o]

// -------- packed f32x2 fma --------
__device__ __forceinline__ void ffma2(ull& acc, ull a, ull b) {
    asm("fma.rn.f32x2 %0, %1, %2, %0;" : "+l"(acc) : "l"(a), "l"(b));
}

// ============================================================
// Kernel P: prep — zero worklist counter + repack weights to
// wpack[b][kk][c][o] for coalesced reads in k_correct.
// grid = 27 blocks (b*9+kk), 64 threads (o).
// ============================================================
__global__ void k_prep(const float* __restrict__ w0,
                       const float* __restrict__ w1,
                       const float* __restrict__ w2) {
    if (blockIdx.x == 0 && threadIdx.x == 0) g_count = 0;
    const int b  = blockIdx.x / 9;
    const int kk = blockIdx.x % 9;
    const float* wb = (b == 0) ? w0 : (b == 1) ? w1 : w2;
    const int o = threadIdx.x;
    float* dst = g_wpack + (size_t)blockIdx.x * (CIN * OUT);
    #pragma unroll 8
    for (int c = 0; c < CIN; ++c)
        dst[c * OUT + o] = wb[o * KWSTRIDE + c * 9 + kk];
}

// ============================================================
// Kernel B: compute rare-tap masks, build worklist.
// One block = one image row (128 pixels), 128 threads.
// ============================================================
__global__ void k_masks(const float* __restrict__ depth,
                        const float* __restrict__ fx) {
    const int n = blockIdx.x >> 7;
    const int h = blockIdx.x & 127;
    const int w = threadIdx.x;

    const float* drow = depth + (size_t)n * HW;
    const float ctr = drow[h * WW + w];
    const float fxv = fx[n];
    const float grid = ctr / fxv;          // IEEE div, matches jnp divide
    const float half = 0.5f * grid;
    const float t0 = ctr + grid;           // branch 0 target
    const float t2 = ctr - grid;           // branch 2 target

    unsigned mask = 0;
    #pragma unroll
    for (int dy = -1; dy <= 1; ++dy) {
        #pragma unroll
        for (int dx = -1; dx <= 1; ++dx) {
            const int kk = (dy + 1) * 3 + (dx + 1);
            if (kk == 4) continue;  // center: m1 always on (dense), m0/m2 provably off
            const int hh = h + dy, ww2 = w + dx;
            if (hh < 0 || hh >= HH || ww2 < 0 || ww2 >= WW) continue; // x padded zero
            const float dv = drow[hh * WW + ww2];
            if (fabsf(dv - t0)  <= half) mask |= 1u << (kk * 3 + 0);
            if (fabsf(dv - ctr) <= half) mask |= 1u << (kk * 3 + 1);
            if (fabsf(dv - t2)  <= half) mask |= 1u << (kk * 3 + 2);
        }
    }
    if (mask) {
        const int pos = atomicAdd(&g_count, 1);
        g_list[pos] = make_uint2((unsigned)(n * HW + h * WW + w), mask);
    }
}

// ============================================================
// Kernel A: dense 1x1 conv, out[n,:,p] = W1_center @ x[n,:,p]
// One block = one image row (128 pixels), 128 threads (4 warps).
// Warp handles 16 output channels; lane tx handles pixel
// pairs (2tx,2tx+1) and (64+2tx,65+2tx) as packed f32x2.
// ============================================================
__global__ void __launch_bounds__(128, 4)
k_dense(const float* __restrict__ x,
        const float* __restrict__ w1,
        float* __restrict__ out) {
    __shared__ ull wsh[CIN * OUT];   // (w,w) duplicated pairs: wsh[c*64 + o]

    const int n = blockIdx.x >> 7;
    const int h = blockIdx.x & 127;
    const int t = threadIdx.x;

    // stage duplicated center-tap weights of branch 1
    for (int idx = t; idx < CIN * OUT; idx += 128) {
        const int c = idx >> 6, o = idx & 63;
        const float wv = w1[o * KWSTRIDE + c * 9 + 4];
        float2 d2 = make_float2(wv, wv);
        wsh[idx] = *reinterpret_cast<ull*>(&d2);
    }
    __syncthreads();

    const int tx = t & 31;
    const int obase = (t >> 5) * 16;

    const float* xbase = x + (size_t)n * CIN * HW + h * WW;

    ull acc0[16], acc1[16];
    #pragma unroll
    for (int j = 0; j < 16; ++j) { acc0[j] = 0ull; acc1[j] = 0ull; }

    // prefetch c=0
    const ull* xp = reinterpret_cast<const ull*>(xbase);
    ull xa = xp[tx];
    ull xb = xp[tx + 32];

    #pragma unroll 2
    for (int c = 0; c < CIN; ++c) {
        ull nxa = 0, nxb = 0;
        if (c + 1 < CIN) {
            const ull* np = reinterpret_cast<const ull*>(xbase + (size_t)(c + 1) * HW);
            nxa = np[tx];
            nxb = np[tx + 32];
        }
        const ulonglong2* wrow =
            reinterpret_cast<const ulonglong2*>(&wsh[c * OUT + obase]);
        #pragma unroll
        for (int j = 0; j < 8; ++j) {
            const ulonglong2 w2 = wrow[j];      // LDS.128: two duplicated weights
            ffma2(acc0[2 * j],     xa, w2.x);
            ffma2(acc1[2 * j],     xb, w2.x);
            ffma2(acc0[2 * j + 1], xa, w2.y);
            ffma2(acc1[2 * j + 1], xb, w2.y);
        }
        xa = nxa; xb = nxb;
    }

    float* obase_p = out + (size_t)(n * OUT + obase) * HW + h * WW;
    #pragma unroll
    for (int j = 0; j < 16; ++j) {
        ull* po = reinterpret_cast<ull*>(obase_p + (size_t)j * HW);
        po[tx]      = acc0[j];
        po[tx + 32] = acc1[j];
    }
}

// ============================================================
// Kernel C: sparse corrections. One worklist item (pixel) at a
// time per block; 64 threads. For each active (tap,branch):
//   stage x[:, h+dy, w+dx] into smem (thread = channel),
//   then thread o accumulates sum_c wpack[b,kk,c,o]*xs[c]
// with wpack reads fully coalesced.
// ============================================================
__global__ void __launch_bounds__(64)
k_correct(const float* __restrict__ x,
          float* __restrict__ out) {
    __shared__ float xs[CIN];
    const int cnt = g_count;
    const int o = threadIdx.x;

    for (int i = blockIdx.x; i < cnt; i += gridDim.x) {
        const uint2 item = g_list[i];
        const unsigned pid = item.x;
        unsigned mask = item.y;
        const int n = pid >> 14;
        const int h = (pid >> 7) & 127;
        const int w = pid & 127;
        const float* xpix = x + (size_t)n * CIN * HW;

        float corr = 0.0f;
        while (mask) {
            const int bit = __ffs(mask) - 1;
            mask &= mask - 1;
            const int kk = bit / 3;
            const int b  = bit % 3;
            const int dy = kk / 3 - 1, dx = kk % 3 - 1;

            __syncthreads();   // protect xs from previous tap's readers
            xs[o] = xpix[(size_t)o * HW + (h + dy) * WW + (w + dx)];
            __syncthreads();

            const float* wp = g_wpack + (size_t)(b * 9 + kk) * (CIN * OUT) + o;
            float s = 0.0f;
            #pragma unroll 16
            for (int c = 0; c < CIN; ++c)
                s += wp[(size_t)c * OUT] * xs[c];
            corr += s;
        }
        out[(size_t)(n * OUT + o) * HW + h * WW + w] += corr;
    }
}

// ============================================================
// launch
// ============================================================
extern "C" void kernel_launch(void* const* d_in, const int* in_sizes, int n_in,
                              void* d_out, int out_size) {
    const float* x     = (const float*)d_in[0];
    const float* depth = (const float*)d_in[1];
    const float* fx    = (const float*)d_in[2];
    const float* w0    = (const float*)d_in[3];
    const float* w1    = (const float*)d_in[4];
    const float* w2    = (const float*)d_in[5];
    float* out = (float*)d_out;

    k_prep<<<27, 64>>>(w0, w1, w2);
    k_masks<<<NB * HH, 128>>>(depth, fx);
    k_dense<<<NB * HH, 128>>>(x, w1, out);
    k_correct<<<1024, 64>>>(x, out);
}

// round 4
// speedup vs baseline: 1.8283x; 1.2433x over previous
#include <cuda_runtime.h>
#include <cuda_bf16.h>
#include <cstdint>

#define NB   8
#define CIN  64
#define OUT  64
#define HH   128
#define WW   128
#define HW   (HH*WW)          // 16384
#define NPIX (NB*HW)          // 131072
#define KWSTRIDE 576          // C*K*K per output channel in weight tensors
#define MAXENTRIES (NPIX * 24)

typedef unsigned long long ull;

// -------- scratch (static __device__, no allocation) --------
__device__ int      g_count;
__device__ unsigned g_list[MAXENTRIES];        // entry = pid<<5 | (kk*3+b)
__device__ float    g_wpack[3 * 9 * CIN * OUT];// wpack[(b*9+kk)*4096 + c*64 + o]

// -------- packed f32x2 fma --------
__device__ __forceinline__ void ffma2(ull& acc, ull a, ull b) {
    asm("fma.rn.f32x2 %0, %1, %2, %0;" : "+l"(acc) : "l"(a), "l"(b));
}

// ============================================================
// Kernel PM: fused prep + masks.
//   blocks 0..26   : repack weights -> wpack[b][kk][c][o]
//   blocks 27..    : per-row mask eval, push (pixel,tap,branch)
//                    entries to g_list.
// g_count is zeroed by a memset node before this kernel.
// ============================================================
__global__ void __launch_bounds__(128)
k_prep_masks(const float* __restrict__ w0,
             const float* __restrict__ w1,
             const float* __restrict__ w2,
             const float* __restrict__ depth,
             const float* __restrict__ fx) {
    if (blockIdx.x < 27) {
        const int b  = blockIdx.x / 9;
        const int kk = blockIdx.x % 9;
        const float* wb = (b == 0) ? w0 : (b == 1) ? w1 : w2;
        float* dst = g_wpack + (size_t)blockIdx.x * (CIN * OUT);
        for (int idx = threadIdx.x; idx < CIN * OUT; idx += 128) {
            const int c = idx >> 6, o = idx & 63;
            dst[idx] = wb[o * KWSTRIDE + c * 9 + kk];
        }
        return;
    }

    const int row = blockIdx.x - 27;
    const int n = row >> 7;
    const int h = row & 127;
    const int w = threadIdx.x;

    const float* drow = depth + (size_t)n * HW;
    const float ctr = drow[h * WW + w];
    const float grid = ctr / fx[n];       // IEEE div, matches jnp divide
    const float half = 0.5f * grid;
    const float t0 = ctr + grid;          // branch 0 target
    const float t2 = ctr - grid;          // branch 2 target
    const unsigned pid = (unsigned)(n * HW + h * WW + w);

    #pragma unroll
    for (int dy = -1; dy <= 1; ++dy) {
        #pragma unroll
        for (int dx = -1; dx <= 1; ++dx) {
            const int kk = (dy + 1) * 3 + (dx + 1);
            if (kk == 4) continue;  // center: m1 always on (dense), m0/m2 provably off
            const int hh = h + dy, ww2 = w + dx;
            if (hh < 0 || hh >= HH || ww2 < 0 || ww2 >= WW) continue; // x zero-padded
            const float dv = drow[hh * WW + ww2];
            if (fabsf(dv - t0) <= half) {
                const int pos = atomicAdd(&g_count, 1);
                g_list[pos] = (pid << 5) | (unsigned)(kk * 3 + 0);
            }
            if (fabsf(dv - ctr) <= half) {
                const int pos = atomicAdd(&g_count, 1);
                g_list[pos] = (pid << 5) | (unsigned)(kk * 3 + 1);
            }
            if (fabsf(dv - t2) <= half) {
                const int pos = atomicAdd(&g_count, 1);
                g_list[pos] = (pid << 5) | (unsigned)(kk * 3 + 2);
            }
        }
    }
}

// ============================================================
// Kernel A: dense 1x1 conv, out[n,:,p] = W1_center @ x[n,:,p]
// One block = one image row (128 pixels), 128 threads (4 warps).
// Warp handles 16 output channels; lane tx handles pixel
// pairs (2tx,2tx+1) and (64+2tx,65+2tx) as packed f32x2.
// Weight smem reads are warp-uniform -> broadcast LDS (N=1).
// ============================================================
__global__ void __launch_bounds__(128, 4)
k_dense(const float* __restrict__ x,
        const float* __restrict__ w1,
        float* __restrict__ out) {
    __shared__ ull wsh[CIN * OUT];   // (w,w) duplicated pairs: wsh[c*64 + o]

    const int n = blockIdx.x >> 7;
    const int h = blockIdx.x & 127;
    const int t = threadIdx.x;

    for (int idx = t; idx < CIN * OUT; idx += 128) {
        const int c = idx >> 6, o = idx & 63;
        const float wv = w1[o * KWSTRIDE + c * 9 + 4];
        float2 d2 = make_float2(wv, wv);
        wsh[idx] = *reinterpret_cast<ull*>(&d2);
    }
    __syncthreads();

    const int tx = t & 31;
    const int obase = (t >> 5) * 16;

    const float* xbase = x + (size_t)n * CIN * HW + h * WW;

    ull acc0[16], acc1[16];
    #pragma unroll
    for (int j = 0; j < 16; ++j) { acc0[j] = 0ull; acc1[j] = 0ull; }

    const ull* xp = reinterpret_cast<const ull*>(xbase);
    ull xa = xp[tx];
    ull xb = xp[tx + 32];

    #pragma unroll 2
    for (int c = 0; c < CIN; ++c) {
        ull nxa = 0, nxb = 0;
        if (c + 1 < CIN) {
            const ull* np = reinterpret_cast<const ull*>(xbase + (size_t)(c + 1) * HW);
            nxa = np[tx];
            nxb = np[tx + 32];
        }
        const ulonglong2* wrow =
            reinterpret_cast<const ulonglong2*>(&wsh[c * OUT + obase]);
        #pragma unroll
        for (int j = 0; j < 8; ++j) {
            const ulonglong2 w2 = wrow[j];
            ffma2(acc0[2 * j],     xa, w2.x);
            ffma2(acc1[2 * j],     xb, w2.x);
            ffma2(acc0[2 * j + 1], xa, w2.y);
            ffma2(acc1[2 * j + 1], xb, w2.y);
        }
        xa = nxa; xb = nxb;
    }

    float* obase_p = out + (size_t)(n * OUT + obase) * HW + h * WW;
    #pragma unroll
    for (int j = 0; j < 16; ++j) {
        ull* po = reinterpret_cast<ull*>(obase_p + (size_t)j * HW);
        po[tx]      = acc0[j];
        po[tx + 32] = acc1[j];
    }
}

// ============================================================
// Kernel C: sparse corrections, ONE WARP PER ENTRY.
// Entry = (pixel, tap kk, branch b). Lane l:
//   holds x[c=l], x[c=l+32] of the tap pixel (registers),
//   owns outputs o=2l, 2l+1.
// Inner loop over c: broadcast x via shfl, read wpack as
// coalesced float2. Accumulate into out with atomicAdd (RED).
// ============================================================
__global__ void __launch_bounds__(256)
k_correct(const float* __restrict__ x,
          float* __restrict__ out) {
    const int cnt = g_count;
    const int lane = threadIdx.x & 31;
    const int gw = (blockIdx.x * blockDim.x + threadIdx.x) >> 5;
    const int nwarps = (gridDim.x * blockDim.x) >> 5;

    for (int i = gw; i < cnt; i += nwarps) {
        const unsigned e = g_list[i];
        const unsigned pid = e >> 5;
        const int bit = (int)(e & 31u);
        const int kk = bit / 3;
        const int b  = bit % 3;
        const int dy = kk / 3 - 1, dx = kk % 3 - 1;
        const int n = (int)(pid >> 14);
        const int h = (int)((pid >> 7) & 127u);
        const int w = (int)(pid & 127u);

        const float* xp = x + (size_t)n * CIN * HW + (size_t)(h + dy) * WW + (w + dx);
        const float x0 = xp[(size_t)lane * HW];
        const float x1 = xp[(size_t)(lane + 32) * HW];

        const float2* wp = reinterpret_cast<const float2*>(
            g_wpack + (size_t)(b * 9 + kk) * (CIN * OUT)) + lane;

        float s0 = 0.0f, s1 = 0.0f;
        #pragma unroll
        for (int c = 0; c < 32; ++c) {
            const float xc = __shfl_sync(0xffffffffu, x0, c);
            const float2 wv = wp[c * 32];          // wpack[c][2l..2l+1]
            s0 = fmaf(wv.x, xc, s0);
            s1 = fmaf(wv.y, xc, s1);
        }
        #pragma unroll
        for (int c = 0; c < 32; ++c) {
            const float xc = __shfl_sync(0xffffffffu, x1, c);
            const float2 wv = wp[(c + 32) * 32];
            s0 = fmaf(wv.x, xc, s0);
            s1 = fmaf(wv.y, xc, s1);
        }

        float* op = out + (size_t)(n * OUT + 2 * lane) * HW + (size_t)h * WW + w;
        atomicAdd(op, s0);
        atomicAdd(op + HW, s1);
    }
}

// ============================================================
// launch
// ============================================================
extern "C" void kernel_launch(void* const* d_in, const int* in_sizes, int n_in,
                              void* d_out, int out_size) {
    const float* x     = (const float*)d_in[0];
    const float* depth = (const float*)d_in[1];
    const float* fx    = (const float*)d_in[2];
    const float* w0    = (const float*)d_in[3];
    const float* w1    = (const float*)d_in[4];
    const float* w2    = (const float*)d_in[5];
    float* out = (float*)d_out;

    void* cnt_ptr = nullptr;
    cudaGetSymbolAddress(&cnt_ptr, g_count);
    cudaMemsetAsync(cnt_ptr, 0, sizeof(int));

    k_prep_masks<<<27 + NB * HH, 128>>>(w0, w1, w2, depth, fx);
    k_dense<<<NB * HH, 128>>>(x, w1, out);
    k_correct<<<512, 256>>>(x, out);
}

// round 6
// speedup vs baseline: 2.5641x; 1.4024x over previous
#include <cuda_runtime.h>
#include <cuda_bf16.h>
#include <cstdint>

#define NB   8
#define CIN  64
#define OUT  64
#define HH   128
#define WW   128
#define HW   (HH*WW)          // 16384
#define NPIX (NB*HW)          // 131072
#define KWSTRIDE 576
#define MAXENTRIES (NPIX * 24)

// -------- scratch (static __device__, no allocation) --------
__device__ int      g_count;
__device__ unsigned g_list[MAXENTRIES];         // entry = pid<<5 | (kk*3+b)
__device__ float    g_wpack[3 * 9 * CIN * OUT]; // wpack[(b*9+kk)*4096 + c*64 + o]

// -------- smem layout for dense kernel (144B padded rows) ----
#define ROWB 144                   // 72 bf16 per row: 64 data + 8 pad
#define SM_A_HI 0
#define SM_A_LO (SM_A_HI + 128 * ROWB)   // 18432
#define SM_B_HI (SM_A_LO + 128 * ROWB)   // 36864
#define SM_B_LO (SM_B_HI + 64 * ROWB)    // 46080
#define SM_TOTAL (SM_B_LO + 64 * ROWB)   // 55296
#define DS_STRIDE 132              // epilogue staging row stride (floats)

__device__ __forceinline__ uint32_t smem_u32(const void* p) {
    uint32_t a;
    asm("{ .reg .u64 t; cvta.to.shared.u64 t, %1; cvt.u32.u64 %0, t; }" : "=r"(a) : "l"(p));
    return a;
}
__device__ __forceinline__ void ldm_x4(uint32_t* r, uint32_t addr) {
    asm volatile("ldmatrix.sync.aligned.m8n8.x4.shared.b16 {%0,%1,%2,%3}, [%4];"
                 : "=r"(r[0]), "=r"(r[1]), "=r"(r[2]), "=r"(r[3]) : "r"(addr));
}
__device__ __forceinline__ void mma16816(float* d, const uint32_t* a,
                                         uint32_t b0, uint32_t b1) {
    asm volatile(
        "mma.sync.aligned.m16n8k16.row.col.f32.bf16.bf16.f32 "
        "{%0,%1,%2,%3}, {%4,%5,%6,%7}, {%8,%9}, {%0,%1,%2,%3};"
        : "+f"(d[0]), "+f"(d[1]), "+f"(d[2]), "+f"(d[3])
        : "r"(a[0]), "r"(a[1]), "r"(a[2]), "r"(a[3]), "r"(b0), "r"(b1));
}

// ============================================================
// Kernel P: repack weights -> wpack[b][kk][c][o] (27 blocks)
// ============================================================
__global__ void __launch_bounds__(128)
k_prep(const float* __restrict__ w0,
       const float* __restrict__ w1,
       const float* __restrict__ w2) {
    const int b  = blockIdx.x / 9;
    const int kk = blockIdx.x % 9;
    const float* wb = (b == 0) ? w0 : (b == 1) ? w1 : w2;
    float* dst = g_wpack + (size_t)blockIdx.x * (CIN * OUT);
    for (int idx = threadIdx.x; idx < CIN * OUT; idx += 128) {
        const int c = idx >> 6, o = idx & 63;
        dst[idx] = wb[o * KWSTRIDE + c * 9 + kk];
    }
}

// ============================================================
// Kernel A: dense 1x1 conv via mma.sync bf16x3 split + masks.
// Block = image row (n,h), 128 threads / 4 warps.
//   D[128 px, 64 out] = A[128 px, 64 ch] * B[64 out, 64 ch]^T
// warp wid: px tiles [wid*32, wid*32+32), all 64 outs.
// ============================================================
__global__ void __launch_bounds__(128)
k_dense_masks(const float* __restrict__ x,
              const float* __restrict__ w1,
              const float* __restrict__ depth,
              const float* __restrict__ fx,
              float* __restrict__ out) {
    extern __shared__ char smem[];
    const uint32_t sb = smem_u32(smem);
    const int t = threadIdx.x;
    const int wid = t >> 5, lane = t & 31;
    const int n = blockIdx.x >> 7;
    const int h = blockIdx.x & 127;

    // ---- stage A = x row (px = t), split hi/lo, packed bf16 pairs ----
    {
        const float* xb = x + (size_t)n * CIN * HW + (size_t)h * WW + t;
        char* arow_h = smem + SM_A_HI + t * ROWB;
        char* arow_l = smem + SM_A_LO + t * ROWB;
        #pragma unroll 8
        for (int c = 0; c < CIN; c += 2) {
            const float v0 = xb[(size_t)c * HW];
            const float v1 = xb[(size_t)(c + 1) * HW];
            const __nv_bfloat16 h0 = __float2bfloat16(v0);
            const __nv_bfloat16 h1 = __float2bfloat16(v1);
            const __nv_bfloat16 l0 = __float2bfloat16(v0 - __bfloat162float(h0));
            const __nv_bfloat16 l1 = __float2bfloat16(v1 - __bfloat162float(h1));
            *reinterpret_cast<uint32_t*>(arow_h + c * 2) =
                (uint32_t)__bfloat16_as_ushort(h0) |
                ((uint32_t)__bfloat16_as_ushort(h1) << 16);
            *reinterpret_cast<uint32_t*>(arow_l + c * 2) =
                (uint32_t)__bfloat16_as_ushort(l0) |
                ((uint32_t)__bfloat16_as_ushort(l1) << 16);
        }
    }

    // ---- stage B^T[o][c] = w1 center taps, split hi/lo ----
    for (int i = t; i < OUT * CIN; i += 128) {
        const int o = i >> 6, c = i & 63;
        const float wv = w1[o * KWSTRIDE + c * 9 + 4];
        const __nv_bfloat16 hi = __float2bfloat16(wv);
        const __nv_bfloat16 lo = __float2bfloat16(wv - __bfloat162float(hi));
        *reinterpret_cast<__nv_bfloat16*>(smem + SM_B_HI + o * ROWB + c * 2) = hi;
        *reinterpret_cast<__nv_bfloat16*>(smem + SM_B_LO + o * ROWB + c * 2) = lo;
    }
    __syncthreads();

    // ---- mask eval + worklist push (overlaps with other warps' MMA) ----
    {
        const int w = t;
        const float* drow = depth + (size_t)n * HW;
        const float ctr = drow[h * WW + w];
        const float grid = ctr / fx[n];
        const float half = 0.5f * grid;
        const float t0 = ctr + grid;
        const float t2 = ctr - grid;
        const unsigned pid = (unsigned)(n * HW + h * WW + w);
        #pragma unroll
        for (int dy = -1; dy <= 1; ++dy) {
            #pragma unroll
            for (int dx = -1; dx <= 1; ++dx) {
                const int kk = (dy + 1) * 3 + (dx + 1);
                if (kk == 4) continue;  // center: dense / provably off
                const int hh = h + dy, ww2 = w + dx;
                if (hh < 0 || hh >= HH || ww2 < 0 || ww2 >= WW) continue;
                const float dv = drow[hh * WW + ww2];
                if (fabsf(dv - t0) <= half) {
                    const int pos = atomicAdd(&g_count, 1);
                    g_list[pos] = (pid << 5) | (unsigned)(kk * 3 + 0);
                }
                if (fabsf(dv - ctr) <= half) {
                    const int pos = atomicAdd(&g_count, 1);
                    g_list[pos] = (pid << 5) | (unsigned)(kk * 3 + 1);
                }
                if (fabsf(dv - t2) <= half) {
                    const int pos = atomicAdd(&g_count, 1);
                    g_list[pos] = (pid << 5) | (unsigned)(kk * 3 + 2);
                }
            }
        }
    }

    // ---- MMA: 3 splits x 4 ksteps x (2 mt x 8 nt) ----
    const int g = lane >> 2;           // accumulator row within tile
    const int tig = lane & 3;
    const int px0 = wid * 32;

    // ldmatrix thread address components
    const int amat = lane >> 3, ar = lane & 7;
    const uint32_t a_off = (uint32_t)((px0 + ((amat & 1) << 3) + ar) * ROWB +
                                      (((amat >> 1) << 3) * 2));
    const uint32_t b_off = (uint32_t)(((((amat >> 1) << 3) + ar) * ROWB) +
                                      ((amat & 1) << 4));

    float acc[2][8][4];
    #pragma unroll
    for (int mt = 0; mt < 2; ++mt)
        #pragma unroll
        for (int nt = 0; nt < 8; ++nt)
            #pragma unroll
            for (int j = 0; j < 4; ++j) acc[mt][nt][j] = 0.0f;

    const uint32_t aoffs[3] = {SM_A_HI, SM_A_HI, SM_A_LO};
    const uint32_t boffs[3] = {SM_B_HI, SM_B_LO, SM_B_HI};

    #pragma unroll
    for (int s = 0; s < 3; ++s) {
        const uint32_t abase = sb + aoffs[s] + a_off;
        const uint32_t bbase = sb + boffs[s] + b_off;
        #pragma unroll
        for (int kt = 0; kt < 4; ++kt) {
            uint32_t a[2][4];
            ldm_x4(a[0], abase + kt * 32);
            ldm_x4(a[1], abase + kt * 32 + 16 * ROWB);
            #pragma unroll
            for (int ntp = 0; ntp < 4; ++ntp) {
                uint32_t b[4];
                ldm_x4(b, bbase + ntp * 16 * ROWB + kt * 32);
                #pragma unroll
                for (int mt = 0; mt < 2; ++mt) {
                    mma16816(acc[mt][2 * ntp],     a[mt], b[0], b[1]);
                    mma16816(acc[mt][2 * ntp + 1], a[mt], b[2], b[3]);
                }
            }
        }
    }

    // ---- epilogue: transpose via smem (reuse A region), coalesced STG ----
    __syncthreads();
    float* Ds = reinterpret_cast<float*>(smem);
    #pragma unroll
    for (int mt = 0; mt < 2; ++mt) {
        #pragma unroll
        for (int nt = 0; nt < 8; ++nt) {
            const int o = nt * 8 + 2 * tig;
            const int px = px0 + mt * 16 + g;
            Ds[o * DS_STRIDE + px]           = acc[mt][nt][0];
            Ds[(o + 1) * DS_STRIDE + px]     = acc[mt][nt][1];
            Ds[o * DS_STRIDE + px + 8]       = acc[mt][nt][2];
            Ds[(o + 1) * DS_STRIDE + px + 8] = acc[mt][nt][3];
        }
    }
    __syncthreads();

    float* op = out + (size_t)(n * OUT) * HW + (size_t)h * WW + t;
    #pragma unroll 8
    for (int o = 0; o < OUT; ++o)
        op[(size_t)o * HW] = Ds[o * DS_STRIDE + t];
}

// ============================================================
// Kernel C: sparse corrections, one warp per (pixel,tap,branch).
// ============================================================
__global__ void __launch_bounds__(256)
k_correct(const float* __restrict__ x,
          float* __restrict__ out) {
    const int cnt = g_count;
    const int lane = threadIdx.x & 31;
    const int gw = (blockIdx.x * blockDim.x + threadIdx.x) >> 5;
    const int nwarps = (gridDim.x * blockDim.x) >> 5;

    for (int i = gw; i < cnt; i += nwarps) {
        const unsigned e = g_list[i];
        const unsigned pid = e >> 5;
        const int bit = (int)(e & 31u);
        const int kk = bit / 3;
        const int b  = bit % 3;
        const int dy = kk / 3 - 1, dx = kk % 3 - 1;
        const int n = (int)(pid >> 14);
        const int h = (int)((pid >> 7) & 127u);
        const int w = (int)(pid & 127u);

        const float* xp = x + (size_t)n * CIN * HW + (size_t)(h + dy) * WW + (w + dx);
        const float x0 = xp[(size_t)lane * HW];
        const float x1 = xp[(size_t)(lane + 32) * HW];

        const float2* wp = reinterpret_cast<const float2*>(
            g_wpack + (size_t)(b * 9 + kk) * (CIN * OUT)) + lane;

        float s0 = 0.0f, s1 = 0.0f;
        #pragma unroll
        for (int c = 0; c < 32; ++c) {
            const float xc = __shfl_sync(0xffffffffu, x0, c);
            const float2 wv = wp[c * 32];
            s0 = fmaf(wv.x, xc, s0);
            s1 = fmaf(wv.y, xc, s1);
        }
        #pragma unroll
        for (int c = 0; c < 32; ++c) {
            const float xc = __shfl_sync(0xffffffffu, x1, c);
            const float2 wv = wp[(c + 32) * 32];
            s0 = fmaf(wv.x, xc, s0);
            s1 = fmaf(wv.y, xc, s1);
        }

        float* op = out + (size_t)(n * OUT + 2 * lane) * HW + (size_t)h * WW + w;
        atomicAdd(op, s0);
        atomicAdd(op + HW, s1);
    }
}

// ============================================================
// launch
// ============================================================
extern "C" void kernel_launch(void* const* d_in, const int* in_sizes, int n_in,
                              void* d_out, int out_size) {
    const float* x     = (const float*)d_in[0];
    const float* depth = (const float*)d_in[1];
    const float* fx    = (const float*)d_in[2];
    const float* w0    = (const float*)d_in[3];
    const float* w1    = (const float*)d_in[4];
    const float* w2    = (const float*)d_in[5];
    float* out = (float*)d_out;

    cudaFuncSetAttribute(k_dense_masks,
                         cudaFuncAttributeMaxDynamicSharedMemorySize, SM_TOTAL);

    void* cnt_ptr = nullptr;
    cudaGetSymbolAddress(&cnt_ptr, g_count);
    cudaMemsetAsync(cnt_ptr, 0, sizeof(int));

    k_prep<<<27, 128>>>(w0, w1, w2);
    k_dense_masks<<<NB * HH, 128, SM_TOTAL>>>(x, w1, depth, fx, out);
    k_correct<<<512, 256>>>(x, out);
}

// round 7
// speedup vs baseline: 2.5659x; 1.0007x over previous
#include <cuda_runtime.h>
#include <cuda_bf16.h>
#include <cstdint>

#define NB   8
#define CIN  64
#define OUT  64
#define HH   128
#define WW   128
#define HW   (HH*WW)          // 16384
#define NPIX (NB*HW)          // 131072
#define KWSTRIDE 576
#define MAXENTRIES (NPIX * 24)

// -------- scratch (static __device__, no allocation) --------
__device__ int      g_count;
__device__ unsigned g_list[MAXENTRIES];         // entry = pid<<5 | (kk*3+b)
__device__ float    g_wpack[3 * 9 * CIN * OUT]; // wpack[(b*9+kk)*4096 + c*64 + o]

// -------- smem layout for dense kernel (144B padded rows) ----
#define ROWB 144                   // 72 bf16 per row: 64 data + 8 pad
#define SM_A_HI 0
#define SM_A_LO (SM_A_HI + 128 * ROWB)   // 18432
#define SM_B_HI (SM_A_LO + 128 * ROWB)   // 36864
#define SM_B_LO (SM_B_HI + 64 * ROWB)    // 46080
#define SM_TOTAL (SM_B_LO + 64 * ROWB)   // 55296
#define DS_STRIDE 132              // epilogue staging row stride (floats)

__device__ __forceinline__ uint32_t smem_u32(const void* p) {
    uint32_t a;
    asm("{ .reg .u64 t; cvta.to.shared.u64 t, %1; cvt.u32.u64 %0, t; }" : "=r"(a) : "l"(p));
    return a;
}
__device__ __forceinline__ void ldm_x4(uint32_t* r, uint32_t addr) {
    asm volatile("ldmatrix.sync.aligned.m8n8.x4.shared.b16 {%0,%1,%2,%3}, [%4];"
                 : "=r"(r[0]), "=r"(r[1]), "=r"(r[2]), "=r"(r[3]) : "r"(addr));
}
__device__ __forceinline__ void mma16816(float* d, const uint32_t* a,
                                         uint32_t b0, uint32_t b1) {
    asm volatile(
        "mma.sync.aligned.m16n8k16.row.col.f32.bf16.bf16.f32 "
        "{%0,%1,%2,%3}, {%4,%5,%6,%7}, {%8,%9}, {%0,%1,%2,%3};"
        : "+f"(d[0]), "+f"(d[1]), "+f"(d[2]), "+f"(d[3])
        : "r"(a[0]), "r"(a[1]), "r"(a[2]), "r"(a[3]), "r"(b0), "r"(b1));
}

// ============================================================
// Kernel P: repack weights -> wpack[b][kk][c][o] (27 blocks)
// ============================================================
__global__ void __launch_bounds__(128)
k_prep(const float* __restrict__ w0,
       const float* __restrict__ w1,
       const float* __restrict__ w2) {
    const int b  = blockIdx.x / 9;
    const int kk = blockIdx.x % 9;
    const float* wb = (b == 0) ? w0 : (b == 1) ? w1 : w2;
    float* dst = g_wpack + (size_t)blockIdx.x * (CIN * OUT);
    for (int idx = threadIdx.x; idx < CIN * OUT; idx += 128) {
        const int c = idx >> 6, o = idx & 63;
        dst[idx] = wb[o * KWSTRIDE + c * 9 + kk];
    }
}

// ============================================================
// Kernel A: dense 1x1 conv via mma.sync bf16x3 split + masks.
// Block = image row (n,h), 128 threads / 4 warps.
//   D[128 px, 64 out] = A[128 px, 64 ch] * B[64 out, 64 ch]^T
// warp wid: px tiles [wid*32, wid*32+32), all 64 outs.
// ============================================================
__global__ void __launch_bounds__(128)
k_dense_masks(const float* __restrict__ x,
              const float* __restrict__ w1,
              const float* __restrict__ depth,
              const float* __restrict__ fx,
              float* __restrict__ out) {
    extern __shared__ char smem[];
    const uint32_t sb = smem_u32(smem);
    const int t = threadIdx.x;
    const int wid = t >> 5, lane = t & 31;
    const int n = blockIdx.x >> 7;
    const int h = blockIdx.x & 127;

    // ---- stage A = x row (px = t), split hi/lo, packed bf16 pairs ----
    {
        const float* xb = x + (size_t)n * CIN * HW + (size_t)h * WW + t;
        char* arow_h = smem + SM_A_HI + t * ROWB;
        char* arow_l = smem + SM_A_LO + t * ROWB;
        #pragma unroll 8
        for (int c = 0; c < CIN; c += 2) {
            const float v0 = xb[(size_t)c * HW];
            const float v1 = xb[(size_t)(c + 1) * HW];
            const __nv_bfloat16 h0 = __float2bfloat16(v0);
            const __nv_bfloat16 h1 = __float2bfloat16(v1);
            const __nv_bfloat16 l0 = __float2bfloat16(v0 - __bfloat162float(h0));
            const __nv_bfloat16 l1 = __float2bfloat16(v1 - __bfloat162float(h1));
            *reinterpret_cast<uint32_t*>(arow_h + c * 2) =
                (uint32_t)__bfloat16_as_ushort(h0) |
                ((uint32_t)__bfloat16_as_ushort(h1) << 16);
            *reinterpret_cast<uint32_t*>(arow_l + c * 2) =
                (uint32_t)__bfloat16_as_ushort(l0) |
                ((uint32_t)__bfloat16_as_ushort(l1) << 16);
        }
    }

    // ---- stage B^T[o][c] = w1 center taps, split hi/lo ----
    for (int i = t; i < OUT * CIN; i += 128) {
        const int o = i >> 6, c = i & 63;
        const float wv = w1[o * KWSTRIDE + c * 9 + 4];
        const __nv_bfloat16 hi = __float2bfloat16(wv);
        const __nv_bfloat16 lo = __float2bfloat16(wv - __bfloat162float(hi));
        *reinterpret_cast<__nv_bfloat16*>(smem + SM_B_HI + o * ROWB + c * 2) = hi;
        *reinterpret_cast<__nv_bfloat16*>(smem + SM_B_LO + o * ROWB + c * 2) = lo;
    }
    __syncthreads();

    // ---- mask eval + worklist push (overlaps with other warps' MMA) ----
    {
        const int w = t;
        const float* drow = depth + (size_t)n * HW;
        const float ctr = drow[h * WW + w];
        const float grid = ctr / fx[n];
        const float half = 0.5f * grid;
        const float t0 = ctr + grid;
        const float t2 = ctr - grid;
        const unsigned pid = (unsigned)(n * HW + h * WW + w);
        #pragma unroll
        for (int dy = -1; dy <= 1; ++dy) {
            #pragma unroll
            for (int dx = -1; dx <= 1; ++dx) {
                const int kk = (dy + 1) * 3 + (dx + 1);
                if (kk == 4) continue;  // center: dense / provably off
                const int hh = h + dy, ww2 = w + dx;
                if (hh < 0 || hh >= HH || ww2 < 0 || ww2 >= WW) continue;
                const float dv = drow[hh * WW + ww2];
                if (fabsf(dv - t0) <= half) {
                    const int pos = atomicAdd(&g_count, 1);
                    g_list[pos] = (pid << 5) | (unsigned)(kk * 3 + 0);
                }
                if (fabsf(dv - ctr) <= half) {
                    const int pos = atomicAdd(&g_count, 1);
                    g_list[pos] = (pid << 5) | (unsigned)(kk * 3 + 1);
                }
                if (fabsf(dv - t2) <= half) {
                    const int pos = atomicAdd(&g_count, 1);
                    g_list[pos] = (pid << 5) | (unsigned)(kk * 3 + 2);
                }
            }
        }
    }

    // ---- MMA: 3 splits x 4 ksteps x (2 mt x 8 nt) ----
    const int g = lane >> 2;           // accumulator row within tile
    const int tig = lane & 3;
    const int px0 = wid * 32;

    // ldmatrix thread address components
    const int amat = lane >> 3, ar = lane & 7;
    const uint32_t a_off = (uint32_t)((px0 + ((amat & 1) << 3) + ar) * ROWB +
                                      (((amat >> 1) << 3) * 2));
    const uint32_t b_off = (uint32_t)(((((amat >> 1) << 3) + ar) * ROWB) +
                                      ((amat & 1) << 4));

    float acc[2][8][4];
    #pragma unroll
    for (int mt = 0; mt < 2; ++mt)
        #pragma unroll
        for (int nt = 0; nt < 8; ++nt)
            #pragma unroll
            for (int j = 0; j < 4; ++j) acc[mt][nt][j] = 0.0f;

    const uint32_t aoffs[3] = {SM_A_HI, SM_A_HI, SM_A_LO};
    const uint32_t boffs[3] = {SM_B_HI, SM_B_LO, SM_B_HI};

    #pragma unroll
    for (int s = 0; s < 3; ++s) {
        const uint32_t abase = sb + aoffs[s] + a_off;
        const uint32_t bbase = sb + boffs[s] + b_off;
        #pragma unroll
        for (int kt = 0; kt < 4; ++kt) {
            uint32_t a[2][4];
            ldm_x4(a[0], abase + kt * 32);
            ldm_x4(a[1], abase + kt * 32 + 16 * ROWB);
            #pragma unroll
            for (int ntp = 0; ntp < 4; ++ntp) {
                uint32_t b[4];
                ldm_x4(b, bbase + ntp * 16 * ROWB + kt * 32);
                #pragma unroll
                for (int mt = 0; mt < 2; ++mt) {
                    mma16816(acc[mt][2 * ntp],     a[mt], b[0], b[1]);
                    mma16816(acc[mt][2 * ntp + 1], a[mt], b[2], b[3]);
                }
            }
        }
    }

    // ---- epilogue: transpose via smem (reuse A region), coalesced STG ----
    __syncthreads();
    float* Ds = reinterpret_cast<float*>(smem);
    #pragma unroll
    for (int mt = 0; mt < 2; ++mt) {
        #pragma unroll
        for (int nt = 0; nt < 8; ++nt) {
            const int o = nt * 8 + 2 * tig;
            const int px = px0 + mt * 16 + g;
            Ds[o * DS_STRIDE + px]           = acc[mt][nt][0];
            Ds[(o + 1) * DS_STRIDE + px]     = acc[mt][nt][1];
            Ds[o * DS_STRIDE + px + 8]       = acc[mt][nt][2];
            Ds[(o + 1) * DS_STRIDE + px + 8] = acc[mt][nt][3];
        }
    }
    __syncthreads();

    float* op = out + (size_t)(n * OUT) * HW + (size_t)h * WW + t;
    #pragma unroll 8
    for (int o = 0; o < OUT; ++o)
        op[(size_t)o * HW] = Ds[o * DS_STRIDE + t];
}

// ============================================================
// Kernel C: sparse corrections, one warp per (pixel,tap,branch).
// ============================================================
__global__ void __launch_bounds__(256)
k_correct(const float* __restrict__ x,
          float* __restrict__ out) {
    const int cnt = g_count;
    const int lane = threadIdx.x & 31;
    const int gw = (blockIdx.x * blockDim.x + threadIdx.x) >> 5;
    const int nwarps = (gridDim.x * blockDim.x) >> 5;

    for (int i = gw; i < cnt; i += nwarps) {
        const unsigned e = g_list[i];
        const unsigned pid = e >> 5;
        const int bit = (int)(e & 31u);
        const int kk = bit / 3;
        const int b  = bit % 3;
        const int dy = kk / 3 - 1, dx = kk % 3 - 1;
        const int n = (int)(pid >> 14);
        const int h = (int)((pid >> 7) & 127u);
        const int w = (int)(pid & 127u);

        const float* xp = x + (size_t)n * CIN * HW + (size_t)(h + dy) * WW + (w + dx);
        const float x0 = xp[(size_t)lane * HW];
        const float x1 = xp[(size_t)(lane + 32) * HW];

        const float2* wp = reinterpret_cast<const float2*>(
            g_wpack + (size_t)(b * 9 + kk) * (CIN * OUT)) + lane;

        float s0 = 0.0f, s1 = 0.0f;
        #pragma unroll
        for (int c = 0; c < 32; ++c) {
            const float xc = __shfl_sync(0xffffffffu, x0, c);
            const float2 wv = wp[c * 32];
            s0 = fmaf(wv.x, xc, s0);
            s1 = fmaf(wv.y, xc, s1);
        }
        #pragma unroll
        for (int c = 0; c < 32; ++c) {
            const float xc = __shfl_sync(0xffffffffu, x1, c);
            const float2 wv = wp[(c + 32) * 32];
            s0 = fmaf(wv.x, xc, s0);
            s1 = fmaf(wv.y, xc, s1);
        }

        float* op = out + (size_t)(n * OUT + 2 * lane) * HW + (size_t)h * WW + w;
        atomicAdd(op, s0);
        atomicAdd(op + HW, s1);
    }
}

// ============================================================
// launch
// ============================================================
extern "C" void kernel_launch(void* const* d_in, const int* in_sizes, int n_in,
                              void* d_out, int out_size) {
    const float* x     = (const float*)d_in[0];
    const float* depth = (const float*)d_in[1];
    const float* fx    = (const float*)d_in[2];
    const float* w0    = (const float*)d_in[3];
    const float* w1    = (const float*)d_in[4];
    const float* w2    = (const float*)d_in[5];
    float* out = (float*)d_out;

    cudaFuncSetAttribute(k_dense_masks,
                         cudaFuncAttributeMaxDynamicSharedMemorySize, SM_TOTAL);

    void* cnt_ptr = nullptr;
    cudaGetSymbolAddress(&cnt_ptr, g_count);
    cudaMemsetAsync(cnt_ptr, 0, sizeof(int));

    k_prep<<<27, 128>>>(w0, w1, w2);
    k_dense_masks<<<NB * HH, 128, SM_TOTAL>>>(x, w1, depth, fx, out);
    k_correct<<<512, 256>>>(x, out);
}